// round 15
// baseline (speedup 1.0000x reference)
#include <cuda_runtime.h>
#include <cuda_fp16.h>
#include <cstdint>
#include <math.h>

#define S 2048
#define VDIM 1024
#define NH 16
#define DH 64

// ---------------- scratch (device globals) ---------------------------------
__device__ __half g_xh[S * VDIM];
__device__ __half g_wqkvh[3 * VDIM * VDIM];
__device__ __half g_wouth[VDIM * VDIM];
__device__ __half g_wposh[VDIM * VDIM];
__device__ __half g_relh[S * VDIM];
__device__ __half g_quh[S * VDIM];
__device__ __half g_qvh[S * VDIM];
__device__ __half g_kh[S * VDIM];
__device__ __half g_relpjh[S * VDIM];
__device__ __half g_vth[VDIM * S];
__device__ __half g_QPh[(size_t)NH * S * S];    // positional logits (fp16)
__device__ __half g_attnh[S * VDIM];

// ---------------- helpers ---------------------------------------------------
__device__ __forceinline__ uint32_t cvta_smem(const void* p) {
    uint32_t a;
    asm("{ .reg .u64 t; cvta.to.shared.u64 t, %1; cvt.u32.u64 %0, t; }" : "=r"(a) : "l"(p));
    return a;
}
#define CP16(smem_u32, gptr) \
    asm volatile("cp.async.cg.shared.global [%0], [%1], 16;" :: "r"(smem_u32), "l"(gptr) : "memory")
#define CP_COMMIT() asm volatile("cp.async.commit_group;" ::: "memory")

__device__ __forceinline__ void mma_f16_16x8x16(float* c, const uint32_t* a, const uint32_t* b) {
    asm volatile(
        "mma.sync.aligned.m16n8k16.row.col.f32.f16.f16.f32 "
        "{%0,%1,%2,%3}, {%4,%5,%6,%7}, {%8,%9}, {%0,%1,%2,%3};"
        : "+f"(c[0]), "+f"(c[1]), "+f"(c[2]), "+f"(c[3])
        : "r"(a[0]), "r"(a[1]), "r"(a[2]), "r"(a[3]), "r"(b[0]), "r"(b[1]));
}

#define STG 3
#define HP 40                      // smem pitch in halfs (80B; conflict-free)

// ---------------------------------------------------------------------------
// fp16 NT GEMM, BM=BN=128, BK=32, 3-stage cp.async, 256 threads, 2 CTAs/SM.
// MODE: 0 = full grid; 2 = anti-upper tiles (br+bc>=15).  OUTH: 0 fp32, 1 fp16.
// ---------------------------------------------------------------------------
template <int MODE, int OUTH>
__global__ __launch_bounds__(256, 2)
void hgemm_nt(const __half* __restrict__ A, int lda, long aStride,
              const __half* __restrict__ B, int ldb, long bStride,
              void* __restrict__ Cv, int ldc, long cStride, int K)
{
    constexpr int BM = 128, BN = 128;
    constexpr int A_STB = BM * HP * 2;
    constexpr int B_STB = BN * HP * 2;
    extern __shared__ __half smh[];
    __half* As = smh;
    __half* Bs = smh + STG * BM * HP;
    const uint32_t sA0 = cvta_smem(As);
    const uint32_t sB0 = cvta_smem(Bs);

    int br, bc;
    if (MODE == 0) {
        br = blockIdx.y; bc = blockIdx.x;
    } else {            // anti-upper tiles: br+bc>=15
        int t = blockIdx.x;
        int r = (int)((sqrtf(8.f * (float)t + 1.f) - 1.f) * 0.5f);
        while ((r + 1) * (r + 2) / 2 <= t) r++;
        while (r * (r + 1) / 2 > t) r--;
        int j = t - r * (r + 1) / 2;
        br = r;
        bc = 15 - r + j;
    }
    const int bz = blockIdx.z;
    A += (long)bz * aStride;
    B += (long)bz * bStride;
    const long row0 = (long)br * BM;
    const long col0 = (long)bc * BN;

    const int NC = K / 32;

    const int tid = threadIdx.x;
    const int wid = tid >> 5, lane = tid & 31;
    const int lq = lane >> 2, lr = lane & 3;
    const int wm0 = (wid >> 2) * 64;
    const int wn0 = (wid & 3) * 32;

    float acc[4][4][4];
#pragma unroll
    for (int i = 0; i < 4; i++)
#pragma unroll
        for (int j = 0; j < 4; j++)
#pragma unroll
            for (int q = 0; q < 4; q++) acc[i][j][q] = 0.f;

    auto load_stage = [&](int c) {
        const int s = c % STG;
        const int k0 = c * 32;
#pragma unroll
        for (int t2 = 0; t2 < 2; t2++) {
            int idx = tid + t2 * 256;
            int row = idx >> 2, kc = idx & 3;
            const __half* g = A + (row0 + row) * (long)lda + k0 + kc * 8;
            CP16(sA0 + (uint32_t)(s * A_STB + row * (HP * 2) + kc * 16), g);
        }
#pragma unroll
        for (int t2 = 0; t2 < 2; t2++) {
            int idx = tid + t2 * 256;
            int row = idx >> 2, kc = idx & 3;
            const __half* g = B + (col0 + row) * (long)ldb + k0 + kc * 8;
            CP16(sB0 + (uint32_t)(s * B_STB + row * (HP * 2) + kc * 16), g);
        }
        CP_COMMIT();
    };

    const int PRO = (NC < STG - 1) ? NC : (STG - 1);
    for (int c = 0; c < PRO; c++) load_stage(c);

    for (int c = 0; c < NC; c++) {
        int n = NC - 1 - c;
        if (n > STG - 2) n = STG - 2;
        if (n == 0) asm volatile("cp.async.wait_group 0;" ::: "memory");
        else        asm volatile("cp.async.wait_group 1;" ::: "memory");
        __syncthreads();
        if (c + STG - 1 < NC) load_stage(c + STG - 1);

        const __half* aS = As + (c % STG) * BM * HP;
        const __half* bS = Bs + (c % STG) * BN * HP;
#pragma unroll
        for (int ks = 0; ks < 2; ks++) {
            const int kk = ks * 16;
            uint32_t af[4][4];
            uint32_t bf[4][2];
#pragma unroll
            for (int mt = 0; mt < 4; mt++) {
                const int m = wm0 + mt * 16 + lq;
                af[mt][0] = *(const uint32_t*)&aS[m * HP + kk + 2 * lr];
                af[mt][1] = *(const uint32_t*)&aS[(m + 8) * HP + kk + 2 * lr];
                af[mt][2] = *(const uint32_t*)&aS[m * HP + kk + 2 * lr + 8];
                af[mt][3] = *(const uint32_t*)&aS[(m + 8) * HP + kk + 2 * lr + 8];
            }
#pragma unroll
            for (int nt = 0; nt < 4; nt++) {
                const int nn = wn0 + nt * 8 + lq;
                bf[nt][0] = *(const uint32_t*)&bS[nn * HP + kk + 2 * lr];
                bf[nt][1] = *(const uint32_t*)&bS[nn * HP + kk + 2 * lr + 8];
            }
#pragma unroll
            for (int mt = 0; mt < 4; mt++)
#pragma unroll
                for (int nt = 0; nt < 4; nt++)
                    mma_f16_16x8x16(acc[mt][nt], af[mt], bf[nt]);
        }
    }

#pragma unroll
    for (int mt = 0; mt < 4; mt++) {
        const long r0 = row0 + wm0 + mt * 16 + lq;
#pragma unroll
        for (int nt = 0; nt < 4; nt++) {
            const int cc = (int)col0 + wn0 + nt * 8 + 2 * lr;
            if (OUTH == 0) {
                float* C = (float*)Cv + (long)bz * cStride;
                *(float2*)&C[r0 * ldc + cc] = make_float2(acc[mt][nt][0], acc[mt][nt][1]);
                *(float2*)&C[(r0 + 8) * ldc + cc] = make_float2(acc[mt][nt][2], acc[mt][nt][3]);
            } else {
                __half* C = (__half*)Cv + (long)bz * cStride;
                *(__half2*)&C[r0 * ldc + cc] = __floats2half2_rn(acc[mt][nt][0], acc[mt][nt][1]);
                *(__half2*)&C[(r0 + 8) * ldc + cc] = __floats2half2_rn(acc[mt][nt][2], acc[mt][nt][3]);
            }
        }
    }
}

// ---------------------------------------------------------------------------
// Mega GEMM: qkv + relproj in one grid (32,16).
// bx 0-7: q-cols -> quh/qvh; 8-15: k-cols -> kh; 16-23: v-cols -> vth
// (transposed); 24-31: relproj (A=relh, B=wposh) -> relpjh.
// ---------------------------------------------------------------------------
__global__ __launch_bounds__(256, 2)
void hgemm_qkvrel(const __half* __restrict__ xh, const __half* __restrict__ wqkvh,
                  const __half* __restrict__ relh, const __half* __restrict__ wposh,
                  const float* __restrict__ uvec, const float* __restrict__ vvec,
                  __half* __restrict__ quh, __half* __restrict__ qvh,
                  __half* __restrict__ kh, __half* __restrict__ vth,
                  __half* __restrict__ relpjh)
{
    constexpr int BM = 128, BN = 128;
    constexpr int A_STB = BM * HP * 2;
    constexpr int B_STB = BN * HP * 2;
    extern __shared__ __half smh[];
    __half* As = smh;
    __half* Bs = smh + STG * BM * HP;
    const uint32_t sA0 = cvta_smem(As);
    const uint32_t sB0 = cvta_smem(Bs);

    const int br = blockIdx.y, bc = blockIdx.x;
    const int type = bc >> 3;                 // 0=q, 1=k, 2=v, 3=relproj
    const long row0 = (long)br * BM;
    const int bcol0 = (type == 3) ? ((bc & 7) * BN) : (bc * BN);
    const __half* Ap = (type == 3) ? relh : xh;
    const __half* Bp = (type == 3) ? wposh : wqkvh;
    const int NC = VDIM / 32;

    const int tid = threadIdx.x;
    const int wid = tid >> 5, lane = tid & 31;
    const int lq = lane >> 2, lr = lane & 3;
    const int wm0 = (wid >> 2) * 64;
    const int wn0 = (wid & 3) * 32;

    float acc[4][4][4];
#pragma unroll
    for (int i = 0; i < 4; i++)
#pragma unroll
        for (int j = 0; j < 4; j++)
#pragma unroll
            for (int q = 0; q < 4; q++) acc[i][j][q] = 0.f;

    auto load_stage = [&](int c) {
        const int s = c % STG;
        const int k0 = c * 32;
#pragma unroll
        for (int t2 = 0; t2 < 2; t2++) {
            int idx = tid + t2 * 256;
            int row = idx >> 2, kc = idx & 3;
            const __half* g = Ap + (row0 + row) * (long)VDIM + k0 + kc * 8;
            CP16(sA0 + (uint32_t)(s * A_STB + row * (HP * 2) + kc * 16), g);
        }
#pragma unroll
        for (int t2 = 0; t2 < 2; t2++) {
            int idx = tid + t2 * 256;
            int row = idx >> 2, kc = idx & 3;
            const __half* g = Bp + (long)(bcol0 + row) * VDIM + k0 + kc * 8;
            CP16(sB0 + (uint32_t)(s * B_STB + row * (HP * 2) + kc * 16), g);
        }
        CP_COMMIT();
    };

    for (int c = 0; c < STG - 1; c++) load_stage(c);

    for (int c = 0; c < NC; c++) {
        int n = NC - 1 - c;
        if (n > STG - 2) n = STG - 2;
        if (n == 0) asm volatile("cp.async.wait_group 0;" ::: "memory");
        else        asm volatile("cp.async.wait_group 1;" ::: "memory");
        __syncthreads();
        if (c + STG - 1 < NC) load_stage(c + STG - 1);

        const __half* aS = As + (c % STG) * BM * HP;
        const __half* bS = Bs + (c % STG) * BN * HP;
#pragma unroll
        for (int ks = 0; ks < 2; ks++) {
            const int kk = ks * 16;
            uint32_t af[4][4];
            uint32_t bf[4][2];
#pragma unroll
            for (int mt = 0; mt < 4; mt++) {
                const int m = wm0 + mt * 16 + lq;
                af[mt][0] = *(const uint32_t*)&aS[m * HP + kk + 2 * lr];
                af[mt][1] = *(const uint32_t*)&aS[(m + 8) * HP + kk + 2 * lr];
                af[mt][2] = *(const uint32_t*)&aS[m * HP + kk + 2 * lr + 8];
                af[mt][3] = *(const uint32_t*)&aS[(m + 8) * HP + kk + 2 * lr + 8];
            }
#pragma unroll
            for (int nt = 0; nt < 4; nt++) {
                const int nn = wn0 + nt * 8 + lq;
                bf[nt][0] = *(const uint32_t*)&bS[nn * HP + kk + 2 * lr];
                bf[nt][1] = *(const uint32_t*)&bS[nn * HP + kk + 2 * lr + 8];
            }
#pragma unroll
            for (int mt = 0; mt < 4; mt++)
#pragma unroll
                for (int nt = 0; nt < 4; nt++)
                    mma_f16_16x8x16(acc[mt][nt], af[mt], bf[nt]);
        }
    }

    if (type == 2) {
        // v: transpose through smem, then write vth[vcol][seq]
        const int colq0 = bcol0 - 2 * VDIM;
        __syncthreads();
        __half* tb = smh;                     // [128 cols][136 pitch]
#pragma unroll
        for (int mt = 0; mt < 4; mt++) {
            const int r = wm0 + mt * 16 + lq;
#pragma unroll
            for (int nt = 0; nt < 4; nt++) {
                const int cc = wn0 + nt * 8 + 2 * lr;
                tb[cc * 136 + r]           = __float2half_rn(acc[mt][nt][0]);
                tb[(cc + 1) * 136 + r]     = __float2half_rn(acc[mt][nt][1]);
                tb[cc * 136 + r + 8]       = __float2half_rn(acc[mt][nt][2]);
                tb[(cc + 1) * 136 + r + 8] = __float2half_rn(acc[mt][nt][3]);
            }
        }
        __syncthreads();
#pragma unroll
        for (int t = 0; t < 8; t++) {
            int idx = tid + t * 256;
            int c = idx >> 4, ch = idx & 15;
            *(float4*)&vth[(long)(colq0 + c) * S + row0 + ch * 8] =
                *(const float4*)&tb[c * 136 + ch * 8];
        }
    } else if (type == 3) {
#pragma unroll
        for (int mt = 0; mt < 4; mt++) {
            const long r0 = row0 + wm0 + mt * 16 + lq;
#pragma unroll
            for (int nt = 0; nt < 4; nt++) {
                const int cc = bcol0 + wn0 + nt * 8 + 2 * lr;
                *(__half2*)&relpjh[r0 * VDIM + cc] =
                    __floats2half2_rn(acc[mt][nt][0], acc[mt][nt][1]);
                *(__half2*)&relpjh[(r0 + 8) * VDIM + cc] =
                    __floats2half2_rn(acc[mt][nt][2], acc[mt][nt][3]);
            }
        }
    } else {
#pragma unroll
        for (int mt = 0; mt < 4; mt++) {
            const long r0 = row0 + wm0 + mt * 16 + lq;
#pragma unroll
            for (int nt = 0; nt < 4; nt++) {
                const int cc = (bcol0 - (type << 10)) + wn0 + nt * 8 + 2 * lr;
                if (type == 0) {
                    const float u0 = uvec[cc], u1 = uvec[cc + 1];
                    const float v0 = vvec[cc], v1 = vvec[cc + 1];
                    *(__half2*)&quh[r0 * VDIM + cc] =
                        __floats2half2_rn(acc[mt][nt][0] + u0, acc[mt][nt][1] + u1);
                    *(__half2*)&quh[(r0 + 8) * VDIM + cc] =
                        __floats2half2_rn(acc[mt][nt][2] + u0, acc[mt][nt][3] + u1);
                    *(__half2*)&qvh[r0 * VDIM + cc] =
                        __floats2half2_rn(acc[mt][nt][0] + v0, acc[mt][nt][1] + v1);
                    *(__half2*)&qvh[(r0 + 8) * VDIM + cc] =
                        __floats2half2_rn(acc[mt][nt][2] + v0, acc[mt][nt][3] + v1);
                } else {
                    *(__half2*)&kh[r0 * VDIM + cc] =
                        __floats2half2_rn(acc[mt][nt][0], acc[mt][nt][1]);
                    *(__half2*)&kh[(r0 + 8) * VDIM + cc] =
                        __floats2half2_rn(acc[mt][nt][2], acc[mt][nt][3]);
                }
            }
        }
    }
}

// ---------------------------------------------------------------------------
// Fused flash attention (QP now fp16)
// ---------------------------------------------------------------------------
#define KSH 18432
#define VSH 17408

__global__ __launch_bounds__(256, 1)
void flash_attn(const __half* __restrict__ quh, const __half* __restrict__ kh,
                const __half* __restrict__ vth, const __half* __restrict__ QP,
                __half* __restrict__ attnh)
{
    extern __shared__ __half sm[];
    __half* qs = sm;
    __half* ks = sm + 128 * 72;
    __half* vs = sm + 3 * 128 * 72;
    const uint32_t qsA = cvta_smem(qs);
    const uint32_t ksA = cvta_smem(ks);
    const uint32_t vsA = cvta_smem(vs);

    const int br = 15 - (int)(blockIdx.x >> 4);
    const int h  = blockIdx.x & 15;
    const int i0 = br * 128;

    const int tid = threadIdx.x;
    const int w = tid >> 5, lane = tid & 31;
    const int lq = lane >> 2, lr = lane & 3;
    const int r0g = i0 + w * 16 + lq;
    const int r1g = r0g + 8;

    auto load_kv = [&](int jt, int buf) {
        const int j0 = jt * 128;
#pragma unroll
        for (int t = 0; t < 4; t++) {
            int idx = tid + t * 256;
            int row = idx >> 3, ch = idx & 7;
            const __half* g = kh + (long)(j0 + row) * VDIM + h * DH + ch * 8;
            CP16(ksA + (uint32_t)(buf * KSH + row * 144 + ch * 16), g);
        }
#pragma unroll
        for (int t = 0; t < 4; t++) {
            int idx = tid + t * 256;
            int row = idx >> 4, ch = idx & 15;
            const __half* g = vth + (long)(h * DH + row) * S + j0 + ch * 8;
            CP16(vsA + (uint32_t)(buf * VSH + row * 272 + ch * 16), g);
        }
        CP_COMMIT();
    };

#pragma unroll
    for (int t = 0; t < 4; t++) {
        int idx = tid + t * 256;
        int row = idx >> 3, ch = idx & 7;
        const __half* g = quh + (long)(i0 + row) * VDIM + h * DH + ch * 8;
        CP16(qsA + (uint32_t)(row * 144 + ch * 16), g);
    }
    CP_COMMIT();
    load_kv(0, 0);
    asm volatile("cp.async.wait_group 0;" ::: "memory");
    __syncthreads();

    uint32_t quA[4][4];
#pragma unroll
    for (int kc = 0; kc < 4; kc++) {
        quA[kc][0] = *(const uint32_t*)&qs[(w * 16 + lq) * 72 + kc * 16 + 2 * lr];
        quA[kc][1] = *(const uint32_t*)&qs[(w * 16 + lq + 8) * 72 + kc * 16 + 2 * lr];
        quA[kc][2] = *(const uint32_t*)&qs[(w * 16 + lq) * 72 + kc * 16 + 2 * lr + 8];
        quA[kc][3] = *(const uint32_t*)&qs[(w * 16 + lq + 8) * 72 + kc * 16 + 2 * lr + 8];
    }

    float O[8][4];
#pragma unroll
    for (int i = 0; i < 8; i++)
#pragma unroll
        for (int q = 0; q < 4; q++) O[i][q] = 0.f;
    float m0 = -1e30f, m1 = -1e30f, l0 = 0.f, l1 = 0.f;

    const __half* qp0 = QP + ((long)h * S + r0g) * S;
    const __half* qp1 = qp0 + 8 * S;

    for (int jt = 0; jt <= br; jt++) {
        if (jt < br) {
            load_kv(jt + 1, (jt + 1) & 1);
            asm volatile("cp.async.wait_group 1;" ::: "memory");
        } else {
            asm volatile("cp.async.wait_group 0;" ::: "memory");
        }
        __syncthreads();

        const __half* ksb = ks + (jt & 1) * (128 * 72);
        const __half* vsb = vs + (jt & 1) * (64 * 136);
        const int j0 = jt * 128;

        float s[16][4];
#pragma unroll
        for (int i = 0; i < 16; i++)
#pragma unroll
            for (int q = 0; q < 4; q++) s[i][q] = 0.f;

#pragma unroll
        for (int kc = 0; kc < 4; kc++)
#pragma unroll
            for (int nt = 0; nt < 16; nt++) {
                uint32_t bb[2];
                bb[0] = *(const uint32_t*)&ksb[(nt * 8 + lq) * 72 + kc * 16 + 2 * lr];
                bb[1] = *(const uint32_t*)&ksb[(nt * 8 + lq) * 72 + kc * 16 + 2 * lr + 8];
                mma_f16_16x8x16(s[nt], quA[kc], bb);
            }

        {
            const int b0 = j0 - r0g - 1 + 2 * S;
            const int b1 = b0 - 8;
#pragma unroll
            for (int nt = 0; nt < 16; nt++) {
                const int jA = nt * 8 + 2 * lr;
                s[nt][0] = (s[nt][0] + __half2float(qp0[(b0 + jA) & (S - 1)])) * 0.125f;
                s[nt][1] = (s[nt][1] + __half2float(qp0[(b0 + jA + 1) & (S - 1)])) * 0.125f;
                s[nt][2] = (s[nt][2] + __half2float(qp1[(b1 + jA) & (S - 1)])) * 0.125f;
                s[nt][3] = (s[nt][3] + __half2float(qp1[(b1 + jA + 1) & (S - 1)])) * 0.125f;
            }
        }
        if (jt == br) {
#pragma unroll
            for (int nt = 0; nt < 16; nt++) {
                const int j = j0 + nt * 8 + 2 * lr;
                if (j > r0g)     s[nt][0] = -1e30f;
                if (j + 1 > r0g) s[nt][1] = -1e30f;
                if (j > r1g)     s[nt][2] = -1e30f;
                if (j + 1 > r1g) s[nt][3] = -1e30f;
            }
        }

        float mx0 = -1e30f, mx1 = -1e30f;
#pragma unroll
        for (int nt = 0; nt < 16; nt++) {
            mx0 = fmaxf(mx0, fmaxf(s[nt][0], s[nt][1]));
            mx1 = fmaxf(mx1, fmaxf(s[nt][2], s[nt][3]));
        }
        mx0 = fmaxf(mx0, __shfl_xor_sync(0xffffffffu, mx0, 1));
        mx0 = fmaxf(mx0, __shfl_xor_sync(0xffffffffu, mx0, 2));
        mx1 = fmaxf(mx1, __shfl_xor_sync(0xffffffffu, mx1, 1));
        mx1 = fmaxf(mx1, __shfl_xor_sync(0xffffffffu, mx1, 2));
        const float m0n = fmaxf(m0, mx0), m1n = fmaxf(m1, mx1);
        const float sc0 = __expf(m0 - m0n), sc1 = __expf(m1 - m1n);
        m0 = m0n; m1 = m1n;

        uint32_t pa[8][4];
        float rs0 = 0.f, rs1 = 0.f;
#pragma unroll
        for (int kc = 0; kc < 8; kc++) {
            float p00 = __expf(s[2 * kc][0] - m0),     p01 = __expf(s[2 * kc][1] - m0);
            float p02 = __expf(s[2 * kc][2] - m1),     p03 = __expf(s[2 * kc][3] - m1);
            float p10 = __expf(s[2 * kc + 1][0] - m0), p11 = __expf(s[2 * kc + 1][1] - m0);
            float p12 = __expf(s[2 * kc + 1][2] - m1), p13 = __expf(s[2 * kc + 1][3] - m1);
            rs0 += p00 + p01 + p10 + p11;
            rs1 += p02 + p03 + p12 + p13;
            *(__half2*)&pa[kc][0] = __floats2half2_rn(p00, p01);
            *(__half2*)&pa[kc][1] = __floats2half2_rn(p02, p03);
            *(__half2*)&pa[kc][2] = __floats2half2_rn(p10, p11);
            *(__half2*)&pa[kc][3] = __floats2half2_rn(p12, p13);
        }
        rs0 += __shfl_xor_sync(0xffffffffu, rs0, 1);
        rs0 += __shfl_xor_sync(0xffffffffu, rs0, 2);
        rs1 += __shfl_xor_sync(0xffffffffu, rs1, 1);
        rs1 += __shfl_xor_sync(0xffffffffu, rs1, 2);
        l0 = l0 * sc0 + rs0;
        l1 = l1 * sc1 + rs1;
#pragma unroll
        for (int nt = 0; nt < 8; nt++) {
            O[nt][0] *= sc0; O[nt][1] *= sc0;
            O[nt][2] *= sc1; O[nt][3] *= sc1;
        }

#pragma unroll
        for (int kc = 0; kc < 8; kc++)
#pragma unroll
            for (int nt = 0; nt < 8; nt++) {
                uint32_t bb[2];
                bb[0] = *(const uint32_t*)&vsb[(nt * 8 + lq) * 136 + kc * 16 + 2 * lr];
                bb[1] = *(const uint32_t*)&vsb[(nt * 8 + lq) * 136 + kc * 16 + 2 * lr + 8];
                mma_f16_16x8x16(O[nt], pa[kc], bb);
            }
        __syncthreads();
    }

    const float il0 = 1.f / l0, il1 = 1.f / l1;
#pragma unroll
    for (int nt = 0; nt < 8; nt++) {
        const int cc = h * DH + nt * 8 + 2 * lr;
        *(__half2*)&attnh[(long)r0g * VDIM + cc] =
            __floats2half2_rn(O[nt][0] * il0, O[nt][1] * il0);
        *(__half2*)&attnh[(long)r1g * VDIM + cc] =
            __floats2half2_rn(O[nt][2] * il1, O[nt][3] * il1);
    }
}

// ---------------------------------------------------------------------------
// aux: convert all fp32 inputs to fp16 in one launch
// ---------------------------------------------------------------------------
#define RN_X   (S * VDIM / 4)
#define RN_WQ  (3 * VDIM * VDIM / 4)
#define RN_WO  (VDIM * VDIM / 4)
#define RN_WP  (VDIM * VDIM / 4)
#define RN_RE  (S * VDIM / 4)
#define RN_TOT (RN_X + RN_WQ + RN_WO + RN_WP + RN_RE)
__global__ __launch_bounds__(256)
void cvt_all(const float* __restrict__ x, __half* __restrict__ xh,
             const float* __restrict__ wq, __half* __restrict__ wqh,
             const float* __restrict__ wo, __half* __restrict__ woh,
             const float* __restrict__ wp, __half* __restrict__ wph,
             const float* __restrict__ re, __half* __restrict__ reh)
{
    int i = blockIdx.x * blockDim.x + threadIdx.x;
    const float* src; __half* dst;
    if (i < RN_X)                       { src = x;  dst = xh; }
    else if ((i -= RN_X) < RN_WQ)       { src = wq; dst = wqh; }
    else if ((i -= RN_WQ) < RN_WO)      { src = wo; dst = woh; }
    else if ((i -= RN_WO) < RN_WP)      { src = wp; dst = wph; }
    else if ((i -= RN_WP) < RN_RE)      { src = re; dst = reh; }
    else return;
    float4 v = ((const float4*)src)[i];
    __half2* d = (__half2*)(dst + (size_t)i * 4);
    d[0] = __floats2half2_rn(v.x, v.y);
    d[1] = __floats2half2_rn(v.z, v.w);
}

// ---------------------------------------------------------------------------
extern "C" void kernel_launch(void* const* d_in, const int* in_sizes, int n_in,
                              void* d_out, int out_size)
{
    const float* x    = (const float*)d_in[0];
    const float* Wqkv = (const float*)d_in[1];
    const float* Wout = (const float*)d_in[2];
    const float* Wpos = (const float*)d_in[3];
    const float* uvec = (const float*)d_in[4];
    const float* vvec = (const float*)d_in[5];
    const float* rel  = (const float*)d_in[6];
    float* out = (float*)d_out;

    __half *xh, *wqkvh, *wouth, *wposh, *relh, *quh, *qvh, *kh, *relpjh, *vth, *QPh, *attnh;
    cudaGetSymbolAddress((void**)&xh,     g_xh);
    cudaGetSymbolAddress((void**)&wqkvh,  g_wqkvh);
    cudaGetSymbolAddress((void**)&wouth,  g_wouth);
    cudaGetSymbolAddress((void**)&wposh,  g_wposh);
    cudaGetSymbolAddress((void**)&relh,   g_relh);
    cudaGetSymbolAddress((void**)&quh,    g_quh);
    cudaGetSymbolAddress((void**)&qvh,    g_qvh);
    cudaGetSymbolAddress((void**)&kh,     g_kh);
    cudaGetSymbolAddress((void**)&relpjh, g_relpjh);
    cudaGetSymbolAddress((void**)&vth,    g_vth);
    cudaGetSymbolAddress((void**)&QPh,    g_QPh);
    cudaGetSymbolAddress((void**)&attnh,  g_attnh);

    const int SMEMG = STG * (128 + 128) * HP * 2;        // 61440
    const int SMEMF = (3 * 128 * 72 + 2 * 64 * 136) * 2; // 90112
    static bool attr_done = false;
    if (!attr_done) {
        cudaFuncSetAttribute(hgemm_nt<0, 0>, cudaFuncAttributeMaxDynamicSharedMemorySize, SMEMG);
        cudaFuncSetAttribute(hgemm_nt<2, 1>, cudaFuncAttributeMaxDynamicSharedMemorySize, SMEMG);
        cudaFuncSetAttribute(hgemm_qkvrel,   cudaFuncAttributeMaxDynamicSharedMemorySize, SMEMG);
        cudaFuncSetAttribute(flash_attn,     cudaFuncAttributeMaxDynamicSharedMemorySize, SMEMF);
        attr_done = true;
    }

    const long SS = (long)S * S;

    // 1) convert all inputs to fp16
    cvt_all<<<(RN_TOT + 255) / 256, 256>>>(x, xh, Wqkv, wqkvh, Wout, wouth,
                                           Wpos, wposh, rel, relh);

    // 2) mega GEMM: qkv (fused qu/qv/k/vt epilogues) + relproj
    hgemm_qkvrel<<<dim3(32, 16, 1), 256, SMEMG>>>(xh, wqkvh, relh, wposh,
                                                  uvec, vvec, quh, qvh, kh,
                                                  vth, relpjh);

    // 3) QP[h] = qv_h @ rel_h^T  (anti-upper tiles; fp16 out)
    hgemm_nt<2, 1><<<dim3(136, 1, 16), 256, SMEMG>>>(
        qvh, VDIM, DH, relpjh, VDIM, DH, QPh, S, SS, DH);

    // 4) fused flash attention (fp16 QP gather)
    flash_attn<<<dim3(256), 256, SMEMF>>>(quh, kh, vth, QPh, attnh);

    // 5) out = attn @ Wout^T  (fp32 out)
    hgemm_nt<0, 0><<<dim3(8, 16, 1), 256, SMEMG>>>(
        attnh, VDIM, 0, wouth, VDIM, 0, out, VDIM, 0, VDIM);
}